// round 13
// baseline (speedup 1.0000x reference)
#include <cuda_runtime.h>
#include <cuda_fp16.h>
#include <cstdint>
#include <cstddef>

#define BM 128
#define BN 256
#define BK 64
#define STAGES 4
#define NT 256

#define CHUNK_A (BM * BK * 2)            // 16384 B
#define CHUNK_B (BN * BK * 2)            // 32768 B
#define STAGE_BYTES (CHUNK_A + CHUNK_B)  // 49152 B

#define MAX_MK (2048LL * 4096LL)
#define MAX_NK (11008LL * 4096LL)

__device__ __align__(256) __half g_xh[MAX_MK];   // x as fp16
__device__ __align__(256) __half g_wh[MAX_NK];   // W dequantized to fp16

// ---------- fused pre-pass: x fp32->fp16 AND W int32->fp16 (ref rounding) ----------
__global__ void prep_kernel(const float* __restrict__ x, long long nxv,
                            const int*   __restrict__ qw,
                            const float* __restrict__ sc,
                            const float* __restrict__ zr,
                            int N, int K, int gs, int nxblocks)
{
    if ((int)blockIdx.x < nxblocks) {
        long long i = ((long long)blockIdx.x * blockDim.x + threadIdx.x) * 8;
        if (i >= nxv) return;
        float4 a = *(const float4*)(x + i);
        float4 b = *(const float4*)(x + i + 4);
        __half2 h0 = __floats2half2_rn(a.x, a.y);
        __half2 h1 = __floats2half2_rn(a.z, a.w);
        __half2 h2 = __floats2half2_rn(b.x, b.y);
        __half2 h3 = __floats2half2_rn(b.z, b.w);
        uint4 v;
        v.x = *(uint32_t*)&h0; v.y = *(uint32_t*)&h1;
        v.z = *(uint32_t*)&h2; v.w = *(uint32_t*)&h3;
        *(uint4*)(g_xh + i) = v;
    } else {
        long long idx = (long long)(blockIdx.x - nxblocks) * blockDim.x + threadIdx.x;
        long long tot = (long long)N * K / 8;
        if (idx >= tot) return;
        const int kc8 = K / 8;
        const int n = (int)(idx / kc8);
        const int k = (int)(idx % kc8) * 8;
        const int g = k / gs;
        __half2 s2 = __half2half2(__float2half_rn(sc[(size_t)g * N + n]));
        __half2 z2 = __half2half2(__float2half_rn(zr[(size_t)g * N + n]));
        const int4 q0 = *(const int4*)(qw + (size_t)n * K + k);
        const int4 q1 = *(const int4*)(qw + (size_t)n * K + k + 4);
        __half2 h0 = __hadd2(__hmul2(__floats2half2_rn((float)q0.x, (float)q0.y), s2), z2);
        __half2 h1 = __hadd2(__hmul2(__floats2half2_rn((float)q0.z, (float)q0.w), s2), z2);
        __half2 h2 = __hadd2(__hmul2(__floats2half2_rn((float)q1.x, (float)q1.y), s2), z2);
        __half2 h3 = __hadd2(__hmul2(__floats2half2_rn((float)q1.z, (float)q1.w), s2), z2);
        uint4 v;
        v.x = *(uint32_t*)&h0; v.y = *(uint32_t*)&h1;
        v.z = *(uint32_t*)&h2; v.w = *(uint32_t*)&h3;
        *(uint4*)(g_wh + (size_t)n * K + k) = v;
    }
}

// ---------------- main: fp16 mma.sync GEMM, f16 accumulate per chunk ----------------
__device__ __forceinline__ uint32_t swz(uint32_t b) {
    return b ^ ((b >> 3) & 0x70);   // conflict-free ldmatrix swizzle
}

__global__ void __launch_bounds__(NT, 1)
hgemm_kernel(const float* __restrict__ bias,
             float*       __restrict__ out,
             int M, int N, int K)
{
    extern __shared__ char smem[];
    const uint32_t a0 = (uint32_t)__cvta_generic_to_shared(smem);

    const int tid  = threadIdx.x;
    const int warp = tid >> 5, lane = tid & 31;
    const int wm = warp & 1;   // 2 warps along M (64 rows each)
    const int wn = warp >> 1;  // 4 warps along N (64 cols each)

    const int m0 = blockIdx.x * BM;
    const int n0 = blockIdx.y * BN;
    const int nsteps = K / BK;

    float acc[4][8][4];
    #pragma unroll
    for (int i = 0; i < 4; i++)
        #pragma unroll
        for (int j = 0; j < 8; j++)
            #pragma unroll
            for (int c = 0; c < 4; c++) acc[i][j][c] = 0.f;

    auto load_stage = [&](int slot, int k0) {
        uint32_t xb = a0 + slot * STAGE_BYTES;
        uint32_t wb = xb + CHUNK_A;
        #pragma unroll
        for (int i = 0; i < 4; i++) {               // A: 1024 x 16B chunks
            int c = tid + i * NT;
            int row = c >> 3, ch = c & 7;
            const __half* src = g_xh + (size_t)(m0 + row) * K + k0 + ch * 8;
            asm volatile("cp.async.cg.shared.global [%0], [%1], 16;"
                         :: "r"(xb + swz(row * 128 + ch * 16)), "l"(src));
        }
        #pragma unroll
        for (int i = 0; i < 8; i++) {               // B: 2048 x 16B chunks
            int c = tid + i * NT;
            int row = c >> 3, ch = c & 7;
            const __half* src = g_wh + (size_t)(n0 + row) * K + k0 + ch * 8;
            asm volatile("cp.async.cg.shared.global [%0], [%1], 16;"
                         :: "r"(wb + swz(row * 128 + ch * 16)), "l"(src));
        }
        asm volatile("cp.async.commit_group;");
    };

    auto compute = [&](int slot) {
        uint32_t xb = a0 + slot * STAGE_BYTES;
        uint32_t wb = xb + CHUNK_A;
        uint32_t hacc[4][8][2];   // f16x2 accumulators, live for one chunk
        #pragma unroll
        for (int ks = 0; ks < 4; ks++) {
            const int k0 = ks * 16;
            uint32_t a[4][4];
            #pragma unroll
            for (int mi = 0; mi < 4; mi++) {
                int row = wm * 64 + mi * 16 + (lane & 15);
                int col = k0 + ((lane >> 4) << 3);
                uint32_t addr = xb + swz(row * 128 + col * 2);
                asm volatile("ldmatrix.sync.aligned.m8n8.x4.shared.b16 {%0,%1,%2,%3}, [%4];"
                             : "=r"(a[mi][0]), "=r"(a[mi][1]), "=r"(a[mi][2]), "=r"(a[mi][3])
                             : "r"(addr));
            }
            uint32_t b[8][2];
            #pragma unroll
            for (int nj = 0; nj < 4; nj++) {
                int row = wn * 64 + nj * 16 + (lane & 7) + ((lane >> 4) << 3);
                int col = k0 + (((lane >> 3) & 1) << 3);
                uint32_t addr = wb + swz(row * 128 + col * 2);
                uint32_t r0, r1, r2, r3;
                asm volatile("ldmatrix.sync.aligned.m8n8.x4.shared.b16 {%0,%1,%2,%3}, [%4];"
                             : "=r"(r0), "=r"(r1), "=r"(r2), "=r"(r3) : "r"(addr));
                b[2 * nj][0] = r0; b[2 * nj][1] = r1;
                b[2 * nj + 1][0] = r2; b[2 * nj + 1][1] = r3;
            }
            if (ks == 0) {
                #pragma unroll
                for (int mi = 0; mi < 4; mi++)
                    #pragma unroll
                    for (int nj = 0; nj < 8; nj++)
                        asm volatile(
                            "mma.sync.aligned.m16n8k16.row.col.f16.f16.f16.f16 "
                            "{%0,%1}, {%2,%3,%4,%5}, {%6,%7}, {%8,%9};"
                            : "=r"(hacc[mi][nj][0]), "=r"(hacc[mi][nj][1])
                            : "r"(a[mi][0]), "r"(a[mi][1]), "r"(a[mi][2]), "r"(a[mi][3]),
                              "r"(b[nj][0]), "r"(b[nj][1]), "r"(0u), "r"(0u));
            } else {
                #pragma unroll
                for (int mi = 0; mi < 4; mi++)
                    #pragma unroll
                    for (int nj = 0; nj < 8; nj++)
                        asm volatile(
                            "mma.sync.aligned.m16n8k16.row.col.f16.f16.f16.f16 "
                            "{%0,%1}, {%2,%3,%4,%5}, {%6,%7}, {%0,%1};"
                            : "+r"(hacc[mi][nj][0]), "+r"(hacc[mi][nj][1])
                            : "r"(a[mi][0]), "r"(a[mi][1]), "r"(a[mi][2]), "r"(a[mi][3]),
                              "r"(b[nj][0]), "r"(b[nj][1]));
            }
        }
        // promote chunk partial (f16) into f32 master accumulators
        #pragma unroll
        for (int mi = 0; mi < 4; mi++)
            #pragma unroll
            for (int nj = 0; nj < 8; nj++) {
                float2 lo = __half22float2(*(__half2*)&hacc[mi][nj][0]);
                float2 hi = __half22float2(*(__half2*)&hacc[mi][nj][1]);
                acc[mi][nj][0] += lo.x;
                acc[mi][nj][1] += lo.y;
                acc[mi][nj][2] += hi.x;
                acc[mi][nj][3] += hi.y;
            }
    };

    #pragma unroll
    for (int p = 0; p < STAGES - 1; p++) load_stage(p, p * BK);

    for (int s = 0; s < nsteps; s++) {
        asm volatile("cp.async.wait_group %0;" :: "n"(STAGES - 2));
        __syncthreads();
        if (s + STAGES - 1 < nsteps)
            load_stage((s + STAGES - 1) % STAGES, (s + STAGES - 1) * BK);
        else
            asm volatile("cp.async.commit_group;");
        compute(s % STAGES);
        // no trailing sync: top-of-loop barrier protects slot reuse
    }

    // epilogue: fp16(acc) + fp16(bias) (ref numerics), widen to fp32 out
    const int mwb = m0 + wm * 64;
    const int nwb = n0 + wn * 64;
    const int grp = lane >> 2, qd = lane & 3;
    #pragma unroll
    for (int mi = 0; mi < 4; mi++) {
        #pragma unroll
        for (int nj = 0; nj < 8; nj++) {
            const int col = nwb + nj * 8 + qd * 2;
            __half hb0 = __float2half_rn(bias[col]);
            __half hb1 = __float2half_rn(bias[col + 1]);
            const int row0 = mwb + mi * 16 + grp;
            float2 v0 = {__half2float(__hadd(__float2half_rn(acc[mi][nj][0]), hb0)),
                         __half2float(__hadd(__float2half_rn(acc[mi][nj][1]), hb1))};
            float2 v1 = {__half2float(__hadd(__float2half_rn(acc[mi][nj][2]), hb0)),
                         __half2float(__hadd(__float2half_rn(acc[mi][nj][3]), hb1))};
            *(float2*)(out + (size_t)row0 * N + col)       = v0;
            *(float2*)(out + (size_t)(row0 + 8) * N + col) = v1;
        }
    }
}

extern "C" void kernel_launch(void* const* d_in, const int* in_sizes, int n_in,
                              void* d_out, int out_size)
{
    // ---- order-agnostic input identification by element count ----
    long long sz[16];
    for (int i = 0; i < n_in && i < 16; i++) sz[i] = in_sizes[i];

    int qw_i = 0;
    for (int i = 1; i < n_in; i++) if (sz[i] > sz[qw_i]) qw_i = i;
    int x_i = -1;
    for (int i = 0; i < n_in; i++)
        if (i != qw_i && (x_i < 0 || sz[i] > sz[x_i])) x_i = i;
    int bias_i = -1;
    for (int i = 0; i < n_in; i++)
        if (i != qw_i && i != x_i && sz[i] > 1 &&
            (bias_i < 0 || sz[i] < sz[bias_i])) bias_i = i;
    int p0 = -1, p1 = -1;
    for (int i = 0; i < n_in; i++)
        if (i != qw_i && i != x_i && i != bias_i && sz[i] > 1) {
            if (p0 < 0) p0 = i; else p1 = i;
        }
    int sc_i, z_i;
    if (bias_i > p1) { sc_i = p0; z_i = p1; }   // dict order
    else             { sc_i = p1; z_i = p0; }   // alphabetical order

    const float* x  = (const float*)d_in[x_i];
    const int*   qw = (const int*)d_in[qw_i];
    const float* sc = (const float*)d_in[sc_i];
    const float* zr = (const float*)d_in[z_i];
    const float* bs = (const float*)d_in[bias_i];

    const int N = (int)sz[bias_i];
    const int K = (int)(sz[qw_i] / N);
    const int M = (int)(sz[x_i] / K);
    const int G = (int)(sz[p0] / N);
    const int gs = K / G;

    if ((long long)M * K > MAX_MK || (long long)N * K > MAX_NK) return;

    // fused pre-pass (single launch)
    {
        long long nx = (long long)M * K;
        int nxblocks = (int)((nx / 8 + 255) / 256);
        long long nw = (long long)N * K / 8;
        int nwblocks = (int)((nw + 255) / 256);
        prep_kernel<<<nxblocks + nwblocks, 256>>>(x, nx, qw, sc, zr, N, K, gs, nxblocks);
    }

    const size_t smem_bytes = (size_t)STAGES * STAGE_BYTES; // 196608 B
    cudaFuncSetAttribute(hgemm_kernel,
                         cudaFuncAttributeMaxDynamicSharedMemorySize, (int)smem_bytes);
    dim3 grid(M / BM, N / BN);   // m fastest -> weight-slice L2 reuse
    hgemm_kernel<<<grid, NT, smem_bytes>>>(bs, (float*)d_out, M, N, K);
}

// round 14
// speedup vs baseline: 1.3012x; 1.3012x over previous
#include <cuda_runtime.h>
#include <cuda_fp16.h>
#include <cstdint>
#include <cstddef>

#define BM 128
#define BN 256
#define BK 64
#define STAGES 4
#define NT 256
#define NSM 148
#define KSPLIT 4

#define CHUNK_A (BM * BK * 2)            // 16384 B
#define CHUNK_B (BN * BK * 2)            // 32768 B
#define STAGE_BYTES (CHUNK_A + CHUNK_B)  // 49152 B

#define MAX_MK (2048LL * 4096LL)
#define MAX_NK (11008LL * 4096LL)

__device__ __align__(256) __half g_xh[MAX_MK];   // x as fp16
__device__ __align__(256) __half g_wh[MAX_NK];   // W dequantized to fp16
__device__ __align__(256) float  g_part[KSPLIT * NSM][BM * BN]; // tail partials

// ---------- fused pre-pass: x fp32->fp16 AND W int32->fp16 (ref rounding) ----------
__global__ void prep_kernel(const float* __restrict__ x, long long nxv,
                            const int*   __restrict__ qw,
                            const float* __restrict__ sc,
                            const float* __restrict__ zr,
                            int N, int K, int gs, int nxblocks)
{
    if ((int)blockIdx.x < nxblocks) {
        long long i = ((long long)blockIdx.x * blockDim.x + threadIdx.x) * 8;
        if (i >= nxv) return;
        float4 a = *(const float4*)(x + i);
        float4 b = *(const float4*)(x + i + 4);
        __half2 h0 = __floats2half2_rn(a.x, a.y);
        __half2 h1 = __floats2half2_rn(a.z, a.w);
        __half2 h2 = __floats2half2_rn(b.x, b.y);
        __half2 h3 = __floats2half2_rn(b.z, b.w);
        uint4 v;
        v.x = *(uint32_t*)&h0; v.y = *(uint32_t*)&h1;
        v.z = *(uint32_t*)&h2; v.w = *(uint32_t*)&h3;
        *(uint4*)(g_xh + i) = v;
    } else {
        long long idx = (long long)(blockIdx.x - nxblocks) * blockDim.x + threadIdx.x;
        long long tot = (long long)N * K / 8;
        if (idx >= tot) return;
        const int kc8 = K / 8;
        const int n = (int)(idx / kc8);
        const int k = (int)(idx % kc8) * 8;
        const int g = k / gs;
        __half2 s2 = __half2half2(__float2half_rn(sc[(size_t)g * N + n]));
        __half2 z2 = __half2half2(__float2half_rn(zr[(size_t)g * N + n]));
        const int4 q0 = *(const int4*)(qw + (size_t)n * K + k);
        const int4 q1 = *(const int4*)(qw + (size_t)n * K + k + 4);
        __half2 h0 = __hadd2(__hmul2(__floats2half2_rn((float)q0.x, (float)q0.y), s2), z2);
        __half2 h1 = __hadd2(__hmul2(__floats2half2_rn((float)q0.z, (float)q0.w), s2), z2);
        __half2 h2 = __hadd2(__hmul2(__floats2half2_rn((float)q1.x, (float)q1.y), s2), z2);
        __half2 h3 = __hadd2(__hmul2(__floats2half2_rn((float)q1.z, (float)q1.w), s2), z2);
        uint4 v;
        v.x = *(uint32_t*)&h0; v.y = *(uint32_t*)&h1;
        v.z = *(uint32_t*)&h2; v.w = *(uint32_t*)&h3;
        *(uint4*)(g_wh + (size_t)n * K + k) = v;
    }
}

// ---------------- main: fp16 mma.sync GEMM (R10 pipeline) ----------------
__device__ __forceinline__ uint32_t swz(uint32_t b) {
    return b ^ ((b >> 3) & 0x70);   // conflict-free ldmatrix swizzle
}

// MODE 0: full-K tiles, epilogue -> out. MODE 1: K-part tiles, epilogue -> g_part.
template<int MODE>
__global__ void __launch_bounds__(NT, 1)
hgemm_kernel(const float* __restrict__ bias,
             float*       __restrict__ out,
             int M, int N, int K,
             int tile_offset, int tiles_m, int tcount, int npc)
{
    extern __shared__ char smem[];
    const uint32_t a0 = (uint32_t)__cvta_generic_to_shared(smem);

    const int tid  = threadIdx.x;
    const int warp = tid >> 5, lane = tid & 31;
    const int wm = warp & 1;   // 2 warps along M (64 rows each)
    const int wn = warp >> 1;  // 4 warps along N (64 cols each)

    int tile_id, chunk0, nchunks, slot_id;
    if (MODE == 0) {
        tile_id = tile_offset + blockIdx.x;
        chunk0 = 0; nchunks = K / BK; slot_id = 0;
    } else {
        const int task = blockIdx.x % tcount;
        const int part = blockIdx.x / tcount;
        tile_id = tile_offset + task;
        chunk0 = part * npc; nchunks = npc;
        slot_id = blockIdx.x;
    }
    const int m0 = (tile_id % tiles_m) * BM;
    const int n0 = (tile_id / tiles_m) * BN;

    float acc[4][8][4];
    #pragma unroll
    for (int i = 0; i < 4; i++)
        #pragma unroll
        for (int j = 0; j < 8; j++)
            #pragma unroll
            for (int c = 0; c < 4; c++) acc[i][j][c] = 0.f;

    auto load_stage = [&](int slot, int kchunk) {
        const int k0 = kchunk * BK;
        uint32_t xb = a0 + slot * STAGE_BYTES;
        uint32_t wb = xb + CHUNK_A;
        #pragma unroll
        for (int i = 0; i < 4; i++) {               // A: 1024 x 16B chunks
            int c = tid + i * NT;
            int row = c >> 3, ch = c & 7;
            const __half* src = g_xh + (size_t)(m0 + row) * K + k0 + ch * 8;
            asm volatile("cp.async.cg.shared.global [%0], [%1], 16;"
                         :: "r"(xb + swz(row * 128 + ch * 16)), "l"(src));
        }
        #pragma unroll
        for (int i = 0; i < 8; i++) {               // B: 2048 x 16B chunks
            int c = tid + i * NT;
            int row = c >> 3, ch = c & 7;
            const __half* src = g_wh + (size_t)(n0 + row) * K + k0 + ch * 8;
            asm volatile("cp.async.cg.shared.global [%0], [%1], 16;"
                         :: "r"(wb + swz(row * 128 + ch * 16)), "l"(src));
        }
        asm volatile("cp.async.commit_group;");
    };

    auto lda = [&](uint32_t xb, int ks, uint32_t a[4][4]) {
        const int k0 = ks * 16;
        #pragma unroll
        for (int mi = 0; mi < 4; mi++) {
            int row = wm * 64 + mi * 16 + (lane & 15);
            int col = k0 + ((lane >> 4) << 3);
            uint32_t addr = xb + swz(row * 128 + col * 2);
            asm volatile("ldmatrix.sync.aligned.m8n8.x4.shared.b16 {%0,%1,%2,%3}, [%4];"
                         : "=r"(a[mi][0]), "=r"(a[mi][1]), "=r"(a[mi][2]), "=r"(a[mi][3])
                         : "r"(addr));
        }
    };
    auto ldb = [&](uint32_t wb, int ks, uint32_t b[8][2]) {
        const int k0 = ks * 16;
        #pragma unroll
        for (int nj = 0; nj < 4; nj++) {
            int row = wn * 64 + nj * 16 + (lane & 7) + ((lane >> 4) << 3);
            int col = k0 + (((lane >> 3) & 1) << 3);
            uint32_t addr = wb + swz(row * 128 + col * 2);
            uint32_t r0, r1, r2, r3;
            asm volatile("ldmatrix.sync.aligned.m8n8.x4.shared.b16 {%0,%1,%2,%3}, [%4];"
                         : "=r"(r0), "=r"(r1), "=r"(r2), "=r"(r3) : "r"(addr));
            b[2 * nj][0] = r0; b[2 * nj][1] = r1;
            b[2 * nj + 1][0] = r2; b[2 * nj + 1][1] = r3;
        }
    };
    auto mma_step = [&](uint32_t a[4][4], uint32_t b[8][2]) {
        #pragma unroll
        for (int mi = 0; mi < 4; mi++)
            #pragma unroll
            for (int nj = 0; nj < 8; nj++) {
                asm volatile(
                    "mma.sync.aligned.m16n8k16.row.col.f32.f16.f16.f32 "
                    "{%0,%1,%2,%3}, {%4,%5,%6,%7}, {%8,%9}, {%0,%1,%2,%3};"
                    : "+f"(acc[mi][nj][0]), "+f"(acc[mi][nj][1]),
                      "+f"(acc[mi][nj][2]), "+f"(acc[mi][nj][3])
                    : "r"(a[mi][0]), "r"(a[mi][1]), "r"(a[mi][2]), "r"(a[mi][3]),
                      "r"(b[nj][0]), "r"(b[nj][1]));
            }
    };

    #pragma unroll
    for (int p = 0; p < STAGES - 1; p++) load_stage(p, chunk0 + p);

    uint32_t aF[2][4][4], bF[2][8][2];

    for (int s = 0; s < nchunks; s++) {
        asm volatile("cp.async.wait_group %0;" :: "n"(STAGES - 2));
        __syncthreads();
        if (s + STAGES - 1 < nchunks)
            load_stage((s + STAGES - 1) % STAGES, chunk0 + s + STAGES - 1);
        else
            asm volatile("cp.async.commit_group;");

        uint32_t xb = a0 + (s % STAGES) * STAGE_BYTES;
        uint32_t wb = xb + CHUNK_A;
        lda(xb, 0, aF[0]);
        ldb(wb, 0, bF[0]);
        #pragma unroll
        for (int ks = 0; ks < 4; ks++) {
            if (ks < 3) {
                lda(xb, ks + 1, aF[(ks + 1) & 1]);
                ldb(wb, ks + 1, bF[(ks + 1) & 1]);
            }
            mma_step(aF[ks & 1], bF[ks & 1]);
        }
        // no trailing sync: top-of-loop barrier protects slot reuse
    }

    const int grp = lane >> 2, qd = lane & 3;
    if (MODE == 0) {
        // epilogue: fp16(acc) + fp16(bias) (ref numerics), widen to fp32 out
        const int mwb = m0 + wm * 64;
        const int nwb = n0 + wn * 64;
        #pragma unroll
        for (int mi = 0; mi < 4; mi++) {
            #pragma unroll
            for (int nj = 0; nj < 8; nj++) {
                const int col = nwb + nj * 8 + qd * 2;
                __half hb0 = __float2half_rn(bias[col]);
                __half hb1 = __float2half_rn(bias[col + 1]);
                const int row0 = mwb + mi * 16 + grp;
                float2 v0 = {__half2float(__hadd(__float2half_rn(acc[mi][nj][0]), hb0)),
                             __half2float(__hadd(__float2half_rn(acc[mi][nj][1]), hb1))};
                float2 v1 = {__half2float(__hadd(__float2half_rn(acc[mi][nj][2]), hb0)),
                             __half2float(__hadd(__float2half_rn(acc[mi][nj][3]), hb1))};
                *(float2*)(out + (size_t)row0 * N + col)       = v0;
                *(float2*)(out + (size_t)(row0 + 8) * N + col) = v1;
            }
        }
    } else {
        // raw fp32 partial into scratch [slot][BM][BN]
        float* dst = g_part[slot_id];
        const int mwb = wm * 64;
        const int nwb = wn * 64;
        #pragma unroll
        for (int mi = 0; mi < 4; mi++) {
            #pragma unroll
            for (int nj = 0; nj < 8; nj++) {
                const int col = nwb + nj * 8 + qd * 2;
                const int row0 = mwb + mi * 16 + grp;
                float2 v0 = {acc[mi][nj][0], acc[mi][nj][1]};
                float2 v1 = {acc[mi][nj][2], acc[mi][nj][3]};
                *(float2*)(dst + (size_t)row0 * BN + col)       = v0;
                *(float2*)(dst + (size_t)(row0 + 8) * BN + col) = v1;
            }
        }
    }
}

// ---------------- merge: sum KSPLIT partials in fixed order + epilogue ----------------
__global__ void merge_kernel(const float* __restrict__ bias,
                             float* __restrict__ out,
                             int N, int tiles_m, int tile_offset, int tcount)
{
    const int t  = blockIdx.x;
    const int rg = blockIdx.y;              // 32 row-groups of 4 rows
    const int tid = threadIdx.x;
    const int tile_id = tile_offset + t;
    const int m0 = (tile_id % tiles_m) * BM;
    const int n0 = (tile_id / tiles_m) * BN;
    const int r = rg * 4 + (tid >> 6);
    const int c = (tid & 63) * 4;
    const size_t off = (size_t)r * BN + c;

    float4 s = *(const float4*)(g_part[t] + off);
    #pragma unroll
    for (int p = 1; p < KSPLIT; p++) {
        float4 q = *(const float4*)(g_part[p * tcount + t] + off);
        s.x += q.x; s.y += q.y; s.z += q.z; s.w += q.w;
    }
    float4 v;
    v.x = __half2float(__hadd(__float2half_rn(s.x), __float2half_rn(bias[n0 + c + 0])));
    v.y = __half2float(__hadd(__float2half_rn(s.y), __float2half_rn(bias[n0 + c + 1])));
    v.z = __half2float(__hadd(__float2half_rn(s.z), __float2half_rn(bias[n0 + c + 2])));
    v.w = __half2float(__hadd(__float2half_rn(s.w), __float2half_rn(bias[n0 + c + 3])));
    *(float4*)(out + (size_t)(m0 + r) * N + n0 + c) = v;
}

extern "C" void kernel_launch(void* const* d_in, const int* in_sizes, int n_in,
                              void* d_out, int out_size)
{
    // ---- order-agnostic input identification by element count ----
    long long sz[16];
    for (int i = 0; i < n_in && i < 16; i++) sz[i] = in_sizes[i];

    int qw_i = 0;
    for (int i = 1; i < n_in; i++) if (sz[i] > sz[qw_i]) qw_i = i;
    int x_i = -1;
    for (int i = 0; i < n_in; i++)
        if (i != qw_i && (x_i < 0 || sz[i] > sz[x_i])) x_i = i;
    int bias_i = -1;
    for (int i = 0; i < n_in; i++)
        if (i != qw_i && i != x_i && sz[i] > 1 &&
            (bias_i < 0 || sz[i] < sz[bias_i])) bias_i = i;
    int p0 = -1, p1 = -1;
    for (int i = 0; i < n_in; i++)
        if (i != qw_i && i != x_i && i != bias_i && sz[i] > 1) {
            if (p0 < 0) p0 = i; else p1 = i;
        }
    int sc_i, z_i;
    if (bias_i > p1) { sc_i = p0; z_i = p1; }   // dict order
    else             { sc_i = p1; z_i = p0; }   // alphabetical order

    const float* x  = (const float*)d_in[x_i];
    const int*   qw = (const int*)d_in[qw_i];
    const float* sc = (const float*)d_in[sc_i];
    const float* zr = (const float*)d_in[z_i];
    const float* bs = (const float*)d_in[bias_i];

    const int N = (int)sz[bias_i];
    const int K = (int)(sz[qw_i] / N);
    const int M = (int)(sz[x_i] / K);
    const int G = (int)(sz[p0] / N);
    const int gs = K / G;

    if ((long long)M * K > MAX_MK || (long long)N * K > MAX_NK) return;

    // fused pre-pass (single launch)
    {
        long long nx = (long long)M * K;
        int nxblocks = (int)((nx / 8 + 255) / 256);
        long long nw = (long long)N * K / 8;
        int nwblocks = (int)((nw + 255) / 256);
        prep_kernel<<<nxblocks + nwblocks, 256>>>(x, nx, qw, sc, zr, N, K, gs, nxblocks);
    }

    const size_t smem_bytes = (size_t)STAGES * STAGE_BYTES; // 196608 B
    cudaFuncSetAttribute(hgemm_kernel<0>,
                         cudaFuncAttributeMaxDynamicSharedMemorySize, (int)smem_bytes);
    cudaFuncSetAttribute(hgemm_kernel<1>,
                         cudaFuncAttributeMaxDynamicSharedMemorySize, (int)smem_bytes);

    const int tiles_m = M / BM;
    const int tiles_n = N / BN;
    const int total   = tiles_m * tiles_n;
    const int nch     = K / BK;

    int tail = total % NSM;
    if (tail == total || tail > NSM || (nch % KSPLIT) != 0) tail = 0;  // fallback: no split
    const int main_tiles = total - tail;
    const int npc = nch / KSPLIT;

    if (main_tiles > 0)
        hgemm_kernel<0><<<main_tiles, NT, smem_bytes>>>(
            bs, (float*)d_out, M, N, K, 0, tiles_m, 0, nch);
    if (tail > 0) {
        hgemm_kernel<1><<<tail * KSPLIT, NT, smem_bytes>>>(
            bs, (float*)d_out, M, N, K, main_tiles, tiles_m, tail, npc);
        merge_kernel<<<dim3(tail, BM / 4), 256>>>(
            bs, (float*)d_out, N, tiles_m, main_tiles, tail);
    }
}